// round 17
// baseline (speedup 1.0000x reference)
#include <cuda_runtime.h>
#include <cuda_bf16.h>
#include <cstdint>

#define N_NODES 50000
#define N_EDGES 800000
#define N_EQUADS (N_EDGES / 4)                  // 200000
#define COOP_GRID 148
#define THREADS 1024
#define GSZ (COOP_GRID * THREADS)
#define SCAN_TILE 1024
#define SCAN_TILES ((N_NODES + SCAN_TILE - 1) / SCAN_TILE)   // 49
#define GEMM_ROWS 64
#define NTILES ((N_NODES + GEMM_ROWS - 1) / GEMM_ROWS)       // 782

// ---- scratch (device globals; no allocs) ----
__device__ int g_deg_i[N_NODES];
__device__ int g_cursor[N_NODES];
__device__ int g_src_bin[N_EDGES];
__device__ int g_scan_val[SCAN_TILES];
__device__ volatile int g_scan_flag[SCAN_TILES];
__device__ int g_ei_is64;
__device__ int g_bar_count;          // self-resets each barrier -> replay-safe
__device__ volatile int g_bar_gen;   // monotonically increasing; relative compare

// ---- smem layout (205 KB) ----
#define GSTRIDE 528
#define SM_BIAS  0                               // 512 B
#define SM_NORM  512                             // 64 rows x 8 slices = 2048 B
#define SM_AHI   2560                            // also scan scratch pre-gemm
#define SM_ALO   (SM_AHI + 64 * GSTRIDE)
#define SM_BHI   (SM_ALO + 64 * GSTRIDE)
#define SM_BLO   (SM_BHI + 128 * GSTRIDE)
#define SM_TOT   (SM_BLO + 128 * GSTRIDE)        // 205312 B

// ---- grid-wide barrier (all COOP_GRID blocks resident) ----
__device__ __forceinline__ void grid_bar() {
    __threadfence();
    __syncthreads();
    if (threadIdx.x == 0) {
        int my = g_bar_gen;
        if (atomicAdd(&g_bar_count, 1) == COOP_GRID - 1) {
            g_bar_count = 0;
            __threadfence();
            g_bar_gen = my + 1;
        } else {
            while (g_bar_gen == my) { }
            __threadfence();
        }
    }
    __syncthreads();
}

__device__ __forceinline__ uint32_t smem_u32(const void* p) {
    uint32_t a;
    asm("{ .reg .u64 t; cvta.to.shared.u64 t, %1; cvt.u32.u64 %0, t; }" : "=r"(a) : "l"(p));
    return a;
}
__device__ __forceinline__ void ldsm_x4(uint32_t& r0, uint32_t& r1, uint32_t& r2,
                                        uint32_t& r3, uint32_t addr) {
    asm volatile("ldmatrix.sync.aligned.m8n8.x4.shared.b16 {%0,%1,%2,%3}, [%4];"
                 : "=r"(r0), "=r"(r1), "=r"(r2), "=r"(r3) : "r"(addr));
}
__device__ __forceinline__ void mma_bf16(float* c, const uint32_t* a, const uint32_t* b) {
    asm volatile(
        "mma.sync.aligned.m16n8k16.row.col.f32.bf16.bf16.f32 "
        "{%0,%1,%2,%3}, {%4,%5,%6,%7}, {%8,%9}, {%0,%1,%2,%3};"
        : "+f"(c[0]), "+f"(c[1]), "+f"(c[2]), "+f"(c[3])
        : "r"(a[0]), "r"(a[1]), "r"(a[2]), "r"(a[3]), "r"(b[0]), "r"(b[1]));
}
__device__ __forceinline__ uint2 cvt_hi4(float4 v) {
    __nv_bfloat162 a = __floats2bfloat162_rn(v.x, v.y);
    __nv_bfloat162 b = __floats2bfloat162_rn(v.z, v.w);
    uint2 r;
    r.x = *reinterpret_cast<uint32_t*>(&a);
    r.y = *reinterpret_cast<uint32_t*>(&b);
    return r;
}
__device__ __forceinline__ uint2 cvt_lo4(float4 v) {
    __nv_bfloat162 a = __floats2bfloat162_rn(v.x, v.y);
    __nv_bfloat162 b = __floats2bfloat162_rn(v.z, v.w);
    float4 l = make_float4(v.x - __bfloat162float(a.x), v.y - __bfloat162float(a.y),
                           v.z - __bfloat162float(b.x), v.w - __bfloat162float(b.y));
    __nv_bfloat162 c = __floats2bfloat162_rn(l.x, l.y);
    __nv_bfloat162 d = __floats2bfloat162_rn(l.z, l.w);
    uint2 r;
    r.x = *reinterpret_cast<uint32_t*>(&c);
    r.y = *reinterpret_cast<uint32_t*>(&d);
    return r;
}

// Load 4 consecutive edges' src and dst ids (quad index eq) with int4 loads.
__device__ __forceinline__ void load_edge_quad(const long long* ei, int eq,
                                               int* s, int* d) {
    if (g_ei_is64) {
        const int4* ps = (const int4*)ei;                 // 2 int4 per 4 int64
        int4 a = __ldg(ps + 2 * eq), b = __ldg(ps + 2 * eq + 1);
        s[0] = a.x; s[1] = a.z; s[2] = b.x; s[3] = b.z;
        const int4* pd = (const int4*)(ei + N_EDGES);
        int4 c = __ldg(pd + 2 * eq), e = __ldg(pd + 2 * eq + 1);
        d[0] = c.x; d[1] = c.z; d[2] = e.x; d[3] = e.z;
    } else {
        const int4* ps = (const int4*)ei;
        int4 a = __ldg(ps + eq);
        s[0] = a.x; s[1] = a.y; s[2] = a.z; s[3] = a.w;
        const int4* pd = (const int4*)((const int*)ei + N_EDGES);
        int4 b = __ldg(pd + eq);
        d[0] = b.x; d[1] = b.y; d[2] = b.z; d[3] = b.w;
    }
}

// ===========================================================================
// THE kernel. Phases: W-stage | zero+probe | hist | lookback-scan | binfill
// (4 grid_bars) then per-owned-tile: {warp-gather neigh -> smem A directly,
// stage x half, bf16-split MMA mainloop, bias+L2-norm epilogue}.
// ===========================================================================
__global__ void __launch_bounds__(THREADS, 1) k_fused(
    const long long* __restrict__ ei,
    const float4*    __restrict__ x4,
    const float4*    __restrict__ W4,     // [128][64] float4 (W[c][k])
    const float*     __restrict__ bias,   // [128]
    float4*          __restrict__ out4)   // [N_NODES][32]
{
    extern __shared__ char smem[];
    const uint32_t sb = smem_u32(smem);
    const int tid  = threadIdx.x;
    const int lane = tid & 31;
    const int wid  = tid >> 5;
    const int gtid = blockIdx.x * THREADS + tid;

    int* s_scan = (int*)(smem + SM_AHI);          // scan scratch (pre-gemm only)
    int* s_ws   = s_scan + SCAN_TILE;             // carry slot etc.

    // ---- phase W: stage W -> B_hi/B_lo + bias (persist across all phases) ----
    for (int i = tid; i < 8192; i += THREADS) {
        int c = i >> 6, k4 = i & 63;
        float4 v = __ldg(W4 + i);
        uint32_t off = (uint32_t)(c * GSTRIDE + k4 * 8);
        *reinterpret_cast<uint2*>(smem + SM_BHI + off) = cvt_hi4(v);
        *reinterpret_cast<uint2*>(smem + SM_BLO + off) = cvt_lo4(v);
    }
    if (tid < 128) ((float*)(smem + SM_BIAS))[tid] = __ldg(bias + tid);

    // ---- phase 0: zero counters + flags + dtype probe ----
    for (int i = gtid; i < N_NODES; i += GSZ) g_deg_i[i] = 0;
    if (gtid < SCAN_TILES) g_scan_flag[gtid] = 0;
    if (gtid == 0) {
        int ok = 1;
        for (int k = 0; k < 64; k++) {
            long long v = ei[k];
            if (v < 0 || v >= N_NODES) { ok = 0; break; }
        }
        g_ei_is64 = ok;
    }
    grid_bar();

    // ---- phase 1: in-degree histogram (4-edge unroll, RED no-return) ----
    for (int eq = gtid; eq < N_EQUADS; eq += GSZ) {
        int s[4], d[4];
        load_edge_quad(ei, eq, s, d);
        #pragma unroll
        for (int j = 0; j < 4; j++)
            if ((unsigned)d[j] < N_NODES) atomicAdd(&g_deg_i[d[j]], 1);
    }
    grid_bar();

    // ---- phase 2: single-pass lookback scan (block b = tile b, b < 49) ----
    if (blockIdx.x < SCAN_TILES) {
        const int vt = blockIdx.x;
        int i = vt * SCAN_TILE + tid;
        int v = (i < N_NODES) ? g_deg_i[i] : 0;
        s_scan[tid] = v;
        __syncthreads();
        int acc = v;
        #pragma unroll
        for (int off = 1; off < SCAN_TILE; off <<= 1) {
            int t = (tid >= off) ? s_scan[tid - off] : 0;
            __syncthreads();
            acc += t;
            s_scan[tid] = acc;
            __syncthreads();
        }
        if (tid == SCAN_TILE - 1) {
            g_scan_val[vt] = acc;             // tile aggregate (inclusive total)
            __threadfence();
            g_scan_flag[vt] = 1;
        }
        if (tid == 0) s_ws[0] = 0;
        __syncthreads();
        if (tid < vt) {                        // vt <= 48 < 1024: one pred/thread
            while (g_scan_flag[tid] == 0) { }
            atomicAdd(&s_ws[0], g_scan_val[tid]);
        }
        __syncthreads();
        if (i < N_NODES) g_cursor[i] = s_ws[0] + acc - v;   // exclusive prefix
    }
    grid_bar();

    // ---- phase 3: bin fill (4-edge unroll, independent ATOMG) ----
    for (int eq = gtid; eq < N_EQUADS; eq += GSZ) {
        int s[4], d[4], p[4];
        load_edge_quad(ei, eq, s, d);
        #pragma unroll
        for (int j = 0; j < 4; j++) {
            bool ok = (unsigned)s[j] < N_NODES && (unsigned)d[j] < N_NODES;
            p[j] = ok ? atomicAdd(&g_cursor[d[j]], 1) : -1;
        }
        #pragma unroll
        for (int j = 0; j < 4; j++)
            if (p[j] >= 0) g_src_bin[p[j]] = s[j];
    }
    grid_bar();   // last global sync: bins complete everywhere

    // ---- fused aggregate + GEMM per owned tile (unchanged from R16) ----
    const int g  = wid >> 3;     // m-group: rows g*16..+15 (0..3)
    const int qn = wid & 7;      // n-eighth: cols qn*16..+15 (0..7)

    const int q = lane >> 3, r = lane & 7;
    const uint32_t aRel = (uint32_t)((g * 16 + (q & 1) * 8 + r) * GSTRIDE + (q >> 1) * 16);
    const uint32_t aHiA = sb + SM_AHI + aRel;
    const uint32_t aLoA = sb + SM_ALO + aRel;
    const uint32_t bRel = (uint32_t)((qn * 16 + (q >> 1) * 8 + r) * GSTRIDE + (q & 1) * 16);
    const uint32_t bHiA = sb + SM_BHI + bRel;
    const uint32_t bLoA = sb + SM_BLO + bRel;

    float2* out2 = (float2*)out4;
    const float* bs = (const float*)(smem + SM_BIAS);
    float* snorm = (float*)(smem + SM_NORM);   // [64 rows][8 slices]

    for (int tile = blockIdx.x; tile < NTILES; tile += COOP_GRID) {
        const int base = tile * GEMM_ROWS;

        // -- aggregate this tile's 64 nodes: warp w -> rows 2w, 2w+1;
        //    result written straight into smem A (k4 = 32+lane) as hi/lo --
        #pragma unroll
        for (int u = 0; u < 2; u++) {
            int rr = wid * 2 + u;
            int n  = base + rr;
            float4 a0 = make_float4(0.f, 0.f, 0.f, 0.f);
            float4 a1 = make_float4(0.f, 0.f, 0.f, 0.f);
            float4 a2 = make_float4(0.f, 0.f, 0.f, 0.f);
            float4 a3 = make_float4(0.f, 0.f, 0.f, 0.f);
            float sc = 0.f;
            if (n < N_NODES) {
                int end = g_cursor[n];
                int deg = g_deg_i[n];
                int beg = end - deg;
                for (int bb = beg; bb < end; bb += 32) {
                    int m = min(32, end - bb);
                    int sv = (bb + lane < end) ? __ldg(g_src_bin + bb + lane) : 0;
                    int j = 0;
                    for (; j + 3 < m; j += 4) {
                        int s0 = __shfl_sync(0xffffffffu, sv, j);
                        int s1 = __shfl_sync(0xffffffffu, sv, j + 1);
                        int s2 = __shfl_sync(0xffffffffu, sv, j + 2);
                        int s3 = __shfl_sync(0xffffffffu, sv, j + 3);
                        float4 v0 = __ldg(x4 + s0 * 32 + lane);
                        float4 v1 = __ldg(x4 + s1 * 32 + lane);
                        float4 v2 = __ldg(x4 + s2 * 32 + lane);
                        float4 v3 = __ldg(x4 + s3 * 32 + lane);
                        a0.x += v0.x; a0.y += v0.y; a0.z += v0.z; a0.w += v0.w;
                        a1.x += v1.x; a1.y += v1.y; a1.z += v1.z; a1.w += v1.w;
                        a2.x += v2.x; a2.y += v2.y; a2.z += v2.z; a2.w += v2.w;
                        a3.x += v3.x; a3.y += v3.y; a3.z += v3.z; a3.w += v3.w;
                    }
                    for (; j < m; j++) {
                        int s0 = __shfl_sync(0xffffffffu, sv, j);
                        float4 v0 = __ldg(x4 + s0 * 32 + lane);
                        a0.x += v0.x; a0.y += v0.y; a0.z += v0.z; a0.w += v0.w;
                    }
                }
                sc = 1.0f / fmaxf((float)deg, 1.0f);
            }
            float4 res = make_float4(((a0.x + a1.x) + (a2.x + a3.x)) * sc,
                                     ((a0.y + a1.y) + (a2.y + a3.y)) * sc,
                                     ((a0.z + a1.z) + (a2.z + a3.z)) * sc,
                                     ((a0.w + a1.w) + (a2.w + a3.w)) * sc);
            uint32_t off = (uint32_t)(rr * GSTRIDE + (32 + lane) * 8);
            *reinterpret_cast<uint2*>(smem + SM_AHI + off) = cvt_hi4(res);
            *reinterpret_cast<uint2*>(smem + SM_ALO + off) = cvt_lo4(res);
        }

        // -- stage x half (k4 0..31): 2048 float4 over 1024 threads --
        for (int i = tid; i < 2048; i += THREADS) {
            int rr = i >> 5, k4 = i & 31;
            int row = base + rr;
            float4 v = make_float4(0.f, 0.f, 0.f, 0.f);
            if (row < N_NODES) v = __ldg(x4 + row * 32 + k4);
            uint32_t off = (uint32_t)(rr * GSTRIDE + k4 * 8);
            *reinterpret_cast<uint2*>(smem + SM_AHI + off) = cvt_hi4(v);
            *reinterpret_cast<uint2*>(smem + SM_ALO + off) = cvt_lo4(v);
        }
        __syncthreads();

        // -- bf16-split MMA mainloop (3 interleaved passes) --
        float c[2][4];
        #pragma unroll
        for (int nt = 0; nt < 2; nt++)
            #pragma unroll
            for (int j = 0; j < 4; j++) c[nt][j] = 0.f;

        #pragma unroll 4
        for (int k = 0; k < 16; k++) {
            uint32_t ah[4], al[4], bh[2][2], bl[2][2];
            ldsm_x4(ah[0], ah[1], ah[2], ah[3], aHiA + k * 32);
            ldsm_x4(al[0], al[1], al[2], al[3], aLoA + k * 32);
            ldsm_x4(bh[0][0], bh[0][1], bh[1][0], bh[1][1], bHiA + k * 32);
            ldsm_x4(bl[0][0], bl[0][1], bl[1][0], bl[1][1], bLoA + k * 32);
            #pragma unroll
            for (int nt = 0; nt < 2; nt++) {
                mma_bf16(c[nt], ah, bh[nt]);
                mma_bf16(c[nt], ah, bl[nt]);
                mma_bf16(c[nt], al, bh[nt]);
            }
        }

        // -- epilogue 1: per-slice partial row norms -> smem --
        #pragma unroll
        for (int h2 = 0; h2 < 2; h2++) {
            float ss = 0.f;
            #pragma unroll
            for (int nt = 0; nt < 2; nt++) {
                int col = qn * 16 + nt * 8 + (lane & 3) * 2;
                float v0 = c[nt][2*h2 + 0] + bs[col + 0];
                float v1 = c[nt][2*h2 + 1] + bs[col + 1];
                ss += v0 * v0 + v1 * v1;
            }
            ss += __shfl_xor_sync(0xffffffffu, ss, 1);
            ss += __shfl_xor_sync(0xffffffffu, ss, 2);
            if ((lane & 3) == 0)
                snorm[(g * 16 + h2 * 8 + (lane >> 2)) * 8 + qn] = ss;
        }
        __syncthreads();

        // -- epilogue 2: combine slices, normalize, store --
        #pragma unroll
        for (int h2 = 0; h2 < 2; h2++) {
            int rl = g * 16 + h2 * 8 + (lane >> 2);
            float ss = ((snorm[rl*8+0] + snorm[rl*8+1]) + (snorm[rl*8+2] + snorm[rl*8+3]))
                     + ((snorm[rl*8+4] + snorm[rl*8+5]) + (snorm[rl*8+6] + snorm[rl*8+7]));
            float sc = 1.0f / fmaxf(sqrtf(ss), 1e-12f);
            int row = base + rl;
            if (row < N_NODES) {
                #pragma unroll
                for (int nt = 0; nt < 2; nt++) {
                    int col = qn * 16 + nt * 8 + (lane & 3) * 2;
                    float v0 = c[nt][2*h2 + 0] + bs[col + 0];
                    float v1 = c[nt][2*h2 + 1] + bs[col + 1];
                    out2[row * 64 + qn * 8 + nt * 4 + (lane & 3)] =
                        make_float2(v0 * sc, v1 * sc);
                }
            }
        }
        __syncthreads();   // snorm/A reused next tile
    }
}

// ---------------------------------------------------------------------------
extern "C" void kernel_launch(void* const* d_in, const int* in_sizes, int n_in,
                              void* d_out, int out_size) {
    const float4*    x4   = (const float4*)d_in[0];
    const long long* ei   = (const long long*)d_in[1];
    const float4*    W4   = (const float4*)d_in[2];
    const float*     bias = (const float*)d_in[3];
    float4*          out4 = (float4*)d_out;

    cudaFuncSetAttribute(k_fused,
                         cudaFuncAttributeMaxDynamicSharedMemorySize, SM_TOT);

    k_fused<<<COOP_GRID, THREADS, SM_TOT>>>(ei, x4, W4, bias, out4);
}